// round 4
// baseline (speedup 1.0000x reference)
#include <cuda_runtime.h>
#include <math.h>

#define N_NODES 50000
#define N_EDGES 800000
#define NHEADS 4
#define NEG_SLOPE 0.2f

// ---------------- static device scratch (no allocs allowed) ----------------
__device__ __align__(16) float g_feat[N_NODES * 256];   // per-layer linear output [N, H*D]
__device__ __align__(16) float g_x1[N_NODES * 128];     // layer-1 output
__device__ __align__(16) float g_x2[N_NODES * 128];     // layer-2 output
__device__ __align__(16) float g_res3[N_NODES * 256];   // layer-3 residual projection
__device__ __align__(16) float g_agg3[N_NODES * 256];   // layer-3 aggregated output
__device__ float g_el[N_NODES * NHEADS];
__device__ float g_er[N_NODES * NHEADS];
__device__ int   g_maxi[N_NODES * NHEADS];
__device__ float g_den[N_NODES * NHEADS];
__device__ float g_eatt[N_EDGES * NHEADS];
__device__ int   g_cnt[N_NODES];
__device__ int   g_off[N_NODES + 1];
__device__ int   g_cur[N_NODES];
__device__ int   g_csrc[N_EDGES];
__device__ int   g_ceid[N_EDGES];

// ---------------- CSR build ----------------
__global__ void zero_cnt_kernel() {
    int i = blockIdx.x * blockDim.x + threadIdx.x;
    if (i < N_NODES) g_cnt[i] = 0;
}

__global__ void hist_kernel(const int* __restrict__ dst) {
    int e = blockIdx.x * blockDim.x + threadIdx.x;
    if (e < N_EDGES) atomicAdd(&g_cnt[dst[e]], 1);
}

// single-block exclusive scan over g_cnt -> g_off, g_cur
__global__ void scan_kernel() {
    __shared__ int s[1024];
    __shared__ int carry;
    int tid = threadIdx.x;
    if (tid == 0) carry = 0;
    __syncthreads();
    for (int base = 0; base < N_NODES; base += 1024) {
        int v = (base + tid < N_NODES) ? g_cnt[base + tid] : 0;
        s[tid] = v;
        __syncthreads();
        #pragma unroll
        for (int off = 1; off < 1024; off <<= 1) {
            int t = (tid >= off) ? s[tid - off] : 0;
            __syncthreads();
            s[tid] += t;
            __syncthreads();
        }
        int incl = s[tid];
        int excl = incl - v;
        if (base + tid < N_NODES) {
            g_off[base + tid] = carry + excl;
            g_cur[base + tid] = carry + excl;
        }
        __syncthreads();
        if (tid == 0) carry += s[1023];
        __syncthreads();
    }
    if (tid == 0) g_off[N_NODES] = carry;
}

__global__ void scatter_kernel(const int* __restrict__ src, const int* __restrict__ dst) {
    int e = blockIdx.x * blockDim.x + threadIdx.x;
    if (e < N_EDGES) {
        int d = dst[e];
        int p = atomicAdd(&g_cur[d], 1);
        g_csrc[p] = src[e];
        g_ceid[p] = e;
    }
}

// ---------------- GEMM: out[N,M] = X[N,128] @ W[128,M], M in {128,256} ------
// tile 64 rows x 128 cols, BK=64 (2 k-phases), 256 threads, 8x4 regs/thread.
__global__ void gemm_kernel(const float* __restrict__ X, const float* __restrict__ W,
                            float* __restrict__ out, int M) {
    __shared__ float As[64 * 64];
    __shared__ float Ws[64 * 128];
    int row0 = blockIdx.x * 64;
    int col0 = blockIdx.y * 128;
    int tid = threadIdx.x;
    int cg = tid & 31;    // 4 cols each -> 128 cols
    int rg = tid >> 5;    // 8 row-groups of 8 rows

    float acc[8][4];
    #pragma unroll
    for (int i = 0; i < 8; i++)
        #pragma unroll
        for (int j = 0; j < 4; j++) acc[i][j] = 0.f;

    for (int kp = 0; kp < 2; kp++) {
        // load A tile: 64 rows x 64 cols = 1024 float4
        #pragma unroll
        for (int i = 0; i < 4; i++) {
            int idx = tid + i * 256;     // 0..1023
            int r = idx >> 4;            // 16 float4 per row
            int c = idx & 15;
            float4 v = make_float4(0.f, 0.f, 0.f, 0.f);
            int gr = row0 + r;
            if (gr < N_NODES) v = *(const float4*)(X + gr * 128 + kp * 64 + c * 4);
            *(float4*)(As + r * 64 + c * 4) = v;
        }
        // load W tile: 64 k-rows x 128 cols = 2048 float4
        #pragma unroll
        for (int i = 0; i < 8; i++) {
            int idx = tid + i * 256;     // 0..2047
            int k = idx >> 5;            // 32 float4 per row
            int c = idx & 31;
            *(float4*)(Ws + k * 128 + c * 4) =
                *(const float4*)(W + (kp * 64 + k) * M + col0 + c * 4);
        }
        __syncthreads();

        #pragma unroll 4
        for (int k = 0; k < 64; k++) {
            float4 w = *(float4*)(Ws + k * 128 + cg * 4);
            #pragma unroll
            for (int rr = 0; rr < 8; rr++) {
                float a = As[(rg * 8 + rr) * 64 + k];
                acc[rr][0] = fmaf(a, w.x, acc[rr][0]);
                acc[rr][1] = fmaf(a, w.y, acc[rr][1]);
                acc[rr][2] = fmaf(a, w.z, acc[rr][2]);
                acc[rr][3] = fmaf(a, w.w, acc[rr][3]);
            }
        }
        __syncthreads();
    }

    #pragma unroll
    for (int rr = 0; rr < 8; rr++) {
        int gr = row0 + rg * 8 + rr;
        if (gr < N_NODES)
            *(float4*)(out + gr * M + col0 + cg * 4) =
                make_float4(acc[rr][0], acc[rr][1], acc[rr][2], acc[rr][3]);
    }
}

// ---------------- el/er: warp per node ----------------
__global__ void lr_kernel(const float* __restrict__ al, const float* __restrict__ ar,
                          int D, int M) {
    int gw = (blockIdx.x * blockDim.x + threadIdx.x) >> 5;
    int lane = threadIdx.x & 31;
    if (gw >= N_NODES) return;
    #pragma unroll
    for (int h = 0; h < NHEADS; h++) {
        float sl = 0.f, sr = 0.f;
        for (int d = lane; d < D; d += 32) {
            float f = g_feat[gw * M + h * D + d];
            sl = fmaf(f, al[h * D + d], sl);
            sr = fmaf(f, ar[h * D + d], sr);
        }
        #pragma unroll
        for (int o = 16; o; o >>= 1) {
            sl += __shfl_xor_sync(0xffffffffu, sl, o);
            sr += __shfl_xor_sync(0xffffffffu, sr, o);
        }
        if (lane == 0) {
            g_el[gw * NHEADS + h] = sl;
            g_er[gw * NHEADS + h] = sr;
        }
    }
}

// ---------------- per-(node,head) init ----------------
__global__ void init_nh_kernel() {
    int i = blockIdx.x * blockDim.x + threadIdx.x;
    if (i < N_NODES * NHEADS) {
        g_maxi[i] = 0x80000000;  // INT_MIN == below all ordered-float keys
        g_den[i] = 0.f;
    }
}

__device__ __forceinline__ int f2ord(float f) {
    int b = __float_as_int(f);
    return b >= 0 ? b : (b ^ 0x7fffffff);
}
__device__ __forceinline__ float ord2f(int k) {
    return __int_as_float(k >= 0 ? k : (k ^ 0x7fffffff));
}

// ---------------- edge pass 1: e = leakyrelu(el[src]+er[dst]); segment max --
__global__ void edge1_kernel(const int* __restrict__ src, const int* __restrict__ dst) {
    int idx = blockIdx.x * blockDim.x + threadIdx.x;
    if (idx >= N_EDGES * NHEADS) return;
    int e = idx >> 2, h = idx & 3;
    int s = src[e], d = dst[e];
    float ev = g_el[s * NHEADS + h] + g_er[d * NHEADS + h];
    ev = ev > 0.f ? ev : NEG_SLOPE * ev;
    g_eatt[idx] = ev;
    atomicMax(&g_maxi[d * NHEADS + h], f2ord(ev));
}

// ---------------- edge pass 2: ex = exp(e - max); segment sum ----------------
__global__ void edge2_kernel(const int* __restrict__ dst) {
    int idx = blockIdx.x * blockDim.x + threadIdx.x;
    if (idx >= N_EDGES * NHEADS) return;
    int e = idx >> 2, h = idx & 3;
    int d = dst[e];
    float m = ord2f(g_maxi[d * NHEADS + h]);
    float ex = expf(g_eatt[idx] - m);
    g_eatt[idx] = ex;
    atomicAdd(&g_den[d * NHEADS + h], ex);
}

// ---------------- aggregation: warp per (node, head), CSR gather -------------
__global__ void aggr_kernel(const float* __restrict__ res, float* __restrict__ out,
                            int D, int M, int relu) {
    int gw = (blockIdx.x * blockDim.x + threadIdx.x) >> 5;
    if (gw >= N_NODES * NHEADS) return;
    int n = gw >> 2, h = gw & 3;
    int lane = threadIdx.x & 31;
    int beg = g_off[n], end = g_off[n + 1];

    float acc0 = 0.f, acc1 = 0.f;
    const float* fb = g_feat + h * D;
    for (int j = beg; j < end; j++) {
        int s = g_csrc[j];
        float w = g_eatt[g_ceid[j] * NHEADS + h];
        const float* fp = fb + s * M;
        acc0 = fmaf(w, fp[lane], acc0);
        if (D == 64) acc1 = fmaf(w, fp[lane + 32], acc1);
    }
    float inv = (end > beg) ? (1.0f / g_den[n * NHEADS + h]) : 0.0f;

    float v0 = fmaf(acc0, inv, res[n * M + h * D + lane]);
    if (relu) v0 = fmaxf(v0, 0.f);
    out[n * M + h * D + lane] = v0;
    if (D == 64) {
        float v1 = fmaf(acc1, inv, res[n * M + h * D + lane + 32]);
        if (relu) v1 = fmaxf(v1, 0.f);
        out[n * M + h * D + lane + 32] = v1;
    }
}

// ---------------- final mean over heads ----------------
__global__ void mean_kernel(float* __restrict__ out) {
    int idx = blockIdx.x * blockDim.x + threadIdx.x;
    if (idx >= N_NODES * 64) return;
    int n = idx >> 6, d = idx & 63;
    const float* p = g_agg3 + n * 256 + d;
    out[idx] = 0.25f * (p[0] + p[64] + p[128] + p[192]);
}

// ---------------- launch ----------------
// NOTE: every device buffer passed as a kernel argument from host code MUST be
// a pointer obtained via cudaGetSymbolAddress (host-side symbol decay gives the
// host shadow address; on GB300 ATS the GPU would silently write to host RAM).
static void run_layer(const float* x_in, float* feat, const float* W, const float* al,
                      const float* ar, const float* res, float* out,
                      const int* src, const int* dst, int D, int relu) {
    int M = NHEADS * D;  // 128 or 256
    dim3 ggrid((N_NODES + 63) / 64, M / 128);
    gemm_kernel<<<ggrid, 256>>>(x_in, W, feat, M);
    lr_kernel<<<(N_NODES * 32 + 255) / 256, 256>>>(al, ar, D, M);
    init_nh_kernel<<<(N_NODES * NHEADS + 255) / 256, 256>>>();
    edge1_kernel<<<(N_EDGES * NHEADS + 255) / 256, 256>>>(src, dst);
    edge2_kernel<<<(N_EDGES * NHEADS + 255) / 256, 256>>>(dst);
    aggr_kernel<<<(N_NODES * NHEADS * 32 + 255) / 256, 256>>>(res, out, D, M, relu);
}

extern "C" void kernel_launch(void* const* d_in, const int* in_sizes, int n_in,
                              void* d_out, int out_size) {
    const float* h     = (const float*)d_in[0];
    const float* W1    = (const float*)d_in[1];
    const float* al1   = (const float*)d_in[2];
    const float* ar1   = (const float*)d_in[3];
    const float* W2    = (const float*)d_in[4];
    const float* al2   = (const float*)d_in[5];
    const float* ar2   = (const float*)d_in[6];
    const float* W3    = (const float*)d_in[7];
    const float* al3   = (const float*)d_in[8];
    const float* ar3   = (const float*)d_in[9];
    const float* resW3 = (const float*)d_in[10];
    const int*   src   = (const int*)d_in[11];
    const int*   dst   = (const int*)d_in[12];
    float* out = (float*)d_out;

    float* g_feat_p; cudaGetSymbolAddress((void**)&g_feat_p, g_feat);
    float* g_x1_p;   cudaGetSymbolAddress((void**)&g_x1_p, g_x1);
    float* g_x2_p;   cudaGetSymbolAddress((void**)&g_x2_p, g_x2);
    float* g_res3_p; cudaGetSymbolAddress((void**)&g_res3_p, g_res3);
    float* g_agg3_p; cudaGetSymbolAddress((void**)&g_agg3_p, g_agg3);

    // CSR build (dst-indexed), reused by all 3 layers
    zero_cnt_kernel<<<(N_NODES + 255) / 256, 256>>>();
    hist_kernel<<<(N_EDGES + 255) / 256, 256>>>(dst);
    scan_kernel<<<1, 1024>>>();
    scatter_kernel<<<(N_EDGES + 255) / 256, 256>>>(src, dst);

    // Layer 1: 128 -> 4x32, residual = input, relu
    run_layer(h, g_feat_p, W1, al1, ar1, h, g_x1_p, src, dst, 32, 1);
    // Layer 2: 128 -> 4x32, residual = input, relu
    run_layer(g_x1_p, g_feat_p, W2, al2, ar2, g_x1_p, g_x2_p, src, dst, 32, 1);
    // Layer 3: 128 -> 4x64, residual = x @ resW3, no act
    {
        dim3 ggrid((N_NODES + 63) / 64, 2);
        gemm_kernel<<<ggrid, 256>>>(g_x2_p, resW3, g_res3_p, 256);
    }
    run_layer(g_x2_p, g_feat_p, W3, al3, ar3, g_res3_p, g_agg3_p, src, dst, 64, 0);

    // mean over heads -> [N, 64]
    mean_kernel<<<(N_NODES * 64 + 255) / 256, 256>>>(out);
}

// round 5
// speedup vs baseline: 1.2699x; 1.2699x over previous
#include <cuda_runtime.h>
#include <math.h>

#define N_NODES 50000
#define N_EDGES 800000
#define NHEADS 4
#define NEG_SLOPE 0.2f

// ---------------- static device scratch (no allocs allowed) ----------------
__device__ __align__(16) float g_feat[N_NODES * 256];   // per-layer linear output [N, H*D]
__device__ __align__(16) float g_x1[N_NODES * 128];     // layer-1 output
__device__ __align__(16) float g_x2[N_NODES * 128];     // layer-2 output
__device__ __align__(16) float g_res3[N_NODES * 256];   // layer-3 residual projection
__device__ __align__(16) float g_agg3[N_NODES * 256];   // layer-3 aggregated output
__device__ float g_el[N_NODES * NHEADS];
__device__ float g_er[N_NODES * NHEADS];
__device__ int   g_cnt[N_NODES];
__device__ int   g_off[N_NODES + 1];
__device__ int   g_cur[N_NODES];
__device__ int   g_csrc[N_EDGES];

// ---------------- CSR build ----------------
__global__ void zero_cnt_kernel() {
    int i = blockIdx.x * blockDim.x + threadIdx.x;
    if (i < N_NODES) g_cnt[i] = 0;
}

__global__ void hist_kernel(const int* __restrict__ dst) {
    int e = blockIdx.x * blockDim.x + threadIdx.x;
    if (e < N_EDGES) atomicAdd(&g_cnt[dst[e]], 1);
}

// single-block exclusive scan over g_cnt -> g_off, g_cur (warp-shuffle two-level)
__global__ void scan_kernel() {
    __shared__ int wsum[32];
    __shared__ int carry_s;
    int tid = threadIdx.x, lane = tid & 31, wid = tid >> 5;
    if (tid == 0) carry_s = 0;
    __syncthreads();
    for (int base = 0; base < N_NODES; base += 1024) {
        int v = (base + tid < N_NODES) ? g_cnt[base + tid] : 0;
        // warp inclusive scan
        int x = v;
        #pragma unroll
        for (int o = 1; o < 32; o <<= 1) {
            int t = __shfl_up_sync(0xffffffffu, x, o);
            if (lane >= o) x += t;
        }
        if (lane == 31) wsum[wid] = x;
        __syncthreads();
        if (wid == 0) {
            int y = wsum[lane];
            #pragma unroll
            for (int o = 1; o < 32; o <<= 1) {
                int t = __shfl_up_sync(0xffffffffu, y, o);
                if (lane >= o) y += t;
            }
            wsum[lane] = y;
        }
        __syncthreads();
        int excl = carry_s + x - v + (wid ? wsum[wid - 1] : 0);
        if (base + tid < N_NODES) {
            g_off[base + tid] = excl;
            g_cur[base + tid] = excl;
        }
        __syncthreads();                 // everyone done reading carry_s / wsum
        if (tid == 0) carry_s += wsum[31];
        __syncthreads();
    }
    if (tid == 0) g_off[N_NODES] = carry_s;
}

__global__ void scatter_kernel(const int* __restrict__ src, const int* __restrict__ dst) {
    int e = blockIdx.x * blockDim.x + threadIdx.x;
    if (e < N_EDGES) {
        int d = dst[e];
        int p = atomicAdd(&g_cur[d], 1);
        g_csrc[p] = src[e];
    }
}

// ---------------- GEMM + fused attention-coefficient epilogue ----------------
// out[N,M] = X[N,128] @ W[128,M].  If DA != 0, also compute
//   el[n,h] = sum_d feat[n,h,d]*al[h,d],  er likewise — note the flattened
//   al index h*DA+d equals the GLOBAL output column, so each thread's 4
//   coefficients are just al[col0 + cg*4 ...]. Each warp owns 8 complete rows,
//   so the head-reduction is a segmented shfl over 8 (DA=32) or 16 (DA=64) lanes.
// tile 64 rows x 128 cols, BK=64 (2 k-phases), 256 threads, 8x4 regs/thread.
__global__ void gemm_kernel(const float* __restrict__ X, const float* __restrict__ W,
                            float* __restrict__ out, int M,
                            const float* __restrict__ al, const float* __restrict__ ar,
                            int DA) {
    __shared__ float As[64 * 64];
    __shared__ float Ws[64 * 128];
    int row0 = blockIdx.x * 64;
    int col0 = blockIdx.y * 128;
    int tid = threadIdx.x;
    int cg = tid & 31;    // 4 cols each -> 128 cols
    int rg = tid >> 5;    // 8 row-groups of 8 rows

    float acc[8][4];
    #pragma unroll
    for (int i = 0; i < 8; i++)
        #pragma unroll
        for (int j = 0; j < 4; j++) acc[i][j] = 0.f;

    for (int kp = 0; kp < 2; kp++) {
        #pragma unroll
        for (int i = 0; i < 4; i++) {
            int idx = tid + i * 256;
            int r = idx >> 4;
            int c = idx & 15;
            float4 v = make_float4(0.f, 0.f, 0.f, 0.f);
            int gr = row0 + r;
            if (gr < N_NODES) v = *(const float4*)(X + gr * 128 + kp * 64 + c * 4);
            *(float4*)(As + r * 64 + c * 4) = v;
        }
        #pragma unroll
        for (int i = 0; i < 8; i++) {
            int idx = tid + i * 256;
            int k = idx >> 5;
            int c = idx & 31;
            *(float4*)(Ws + k * 128 + c * 4) =
                *(const float4*)(W + (kp * 64 + k) * M + col0 + c * 4);
        }
        __syncthreads();

        #pragma unroll 4
        for (int k = 0; k < 64; k++) {
            float4 w = *(float4*)(Ws + k * 128 + cg * 4);
            #pragma unroll
            for (int rr = 0; rr < 8; rr++) {
                float a = As[(rg * 8 + rr) * 64 + k];
                acc[rr][0] = fmaf(a, w.x, acc[rr][0]);
                acc[rr][1] = fmaf(a, w.y, acc[rr][1]);
                acc[rr][2] = fmaf(a, w.z, acc[rr][2]);
                acc[rr][3] = fmaf(a, w.w, acc[rr][3]);
            }
        }
        __syncthreads();
    }

    #pragma unroll
    for (int rr = 0; rr < 8; rr++) {
        int gr = row0 + rg * 8 + rr;
        if (gr < N_NODES)
            *(float4*)(out + gr * M + col0 + cg * 4) =
                make_float4(acc[rr][0], acc[rr][1], acc[rr][2], acc[rr][3]);
    }

    if (DA) {
        int col = col0 + cg * 4;
        float4 alv = *(const float4*)(al + col);
        float4 arv = *(const float4*)(ar + col);
        int h = col / DA;                    // global head index
        int grpmask = (DA == 32) ? 7 : 15;   // lanes per head - 1
        #pragma unroll
        for (int rr = 0; rr < 8; rr++) {
            float pl = acc[rr][0] * alv.x + acc[rr][1] * alv.y +
                       acc[rr][2] * alv.z + acc[rr][3] * alv.w;
            float pr = acc[rr][0] * arv.x + acc[rr][1] * arv.y +
                       acc[rr][2] * arv.z + acc[rr][3] * arv.w;
            #pragma unroll
            for (int o = 1; o < 8; o <<= 1) {
                pl += __shfl_xor_sync(0xffffffffu, pl, o);
                pr += __shfl_xor_sync(0xffffffffu, pr, o);
            }
            if (DA == 64) {
                pl += __shfl_xor_sync(0xffffffffu, pl, 8);
                pr += __shfl_xor_sync(0xffffffffu, pr, 8);
            }
            int gr = row0 + rg * 8 + rr;
            if (gr < N_NODES && (cg & grpmask) == 0) {
                g_el[gr * NHEADS + h] = pl;
                g_er[gr * NHEADS + h] = pr;
            }
        }
    }
}

// ---------------- fused edge softmax + aggregation ----------------
// one warp per (node, head); lanes span the feature dim (D=32 or 2x32).
// pass 1: segment max across this node's CSR edges (lanes parallel over edges).
// pass 2: per-32-edge chunk, each lane computes its edge's exp-weight, then the
// warp broadcasts (w, src) via shfl and gathers feat[src] coalesced.
// No intermediate edge buffer, no atomics.
__global__ void attn_aggr_kernel(const float* __restrict__ res, float* __restrict__ out,
                                 int D, int M, int relu) {
    int gw = (blockIdx.x * blockDim.x + threadIdx.x) >> 5;
    if (gw >= N_NODES * NHEADS) return;
    int n = gw >> 2, h = gw & 3;
    int lane = threadIdx.x & 31;
    int beg = g_off[n], end = g_off[n + 1];

    float erv = g_er[n * NHEADS + h];

    float m = -1e30f;
    for (int j = beg + lane; j < end; j += 32) {
        int s = g_csrc[j];
        float e = g_el[s * NHEADS + h] + erv;
        e = e > 0.f ? e : NEG_SLOPE * e;
        m = fmaxf(m, e);
    }
    #pragma unroll
    for (int o = 16; o; o >>= 1) m = fmaxf(m, __shfl_xor_sync(0xffffffffu, m, o));

    float den = 0.f, acc0 = 0.f, acc1 = 0.f;
    for (int j0 = beg; j0 < end; j0 += 32) {
        int j = j0 + lane;
        float w = 0.f;
        int s = 0;
        if (j < end) {
            s = g_csrc[j];
            float e = g_el[s * NHEADS + h] + erv;
            e = e > 0.f ? e : NEG_SLOPE * e;
            w = __expf(e - m);      // e <= m, no overflow
        }
        den += w;
        int cnt = min(32, end - j0);
        for (int t = 0; t < cnt; t++) {
            float wt = __shfl_sync(0xffffffffu, w, t);
            int st = __shfl_sync(0xffffffffu, s, t);
            const float* fp = g_feat + st * M + h * D;
            acc0 = fmaf(wt, fp[lane], acc0);
            if (D == 64) acc1 = fmaf(wt, fp[lane + 32], acc1);
        }
    }
    #pragma unroll
    for (int o = 16; o; o >>= 1) den += __shfl_xor_sync(0xffffffffu, den, o);
    float inv = (end > beg) ? (1.f / den) : 0.f;

    int base = n * M + h * D;
    float v0 = fmaf(acc0, inv, res[base + lane]);
    if (relu) v0 = fmaxf(v0, 0.f);
    out[base + lane] = v0;
    if (D == 64) {
        float v1 = fmaf(acc1, inv, res[base + lane + 32]);
        if (relu) v1 = fmaxf(v1, 0.f);
        out[base + lane + 32] = v1;
    }
}

// ---------------- final mean over heads ----------------
__global__ void mean_kernel(float* __restrict__ out) {
    int idx = blockIdx.x * blockDim.x + threadIdx.x;
    if (idx >= N_NODES * 64) return;
    int n = idx >> 6, d = idx & 63;
    const float* p = g_agg3 + n * 256 + d;
    out[idx] = 0.25f * (p[0] + p[64] + p[128] + p[192]);
}

// ---------------- launch ----------------
// NOTE: every device buffer passed as a kernel argument from host code MUST be
// a pointer obtained via cudaGetSymbolAddress (host-side symbol decay gives the
// host shadow address; on GB300 ATS the GPU would silently write to host RAM).
static void run_layer(const float* x_in, float* feat, const float* W, const float* al,
                      const float* ar, const float* res, float* out, int D, int relu) {
    int M = NHEADS * D;  // 128 or 256
    dim3 ggrid((N_NODES + 63) / 64, M / 128);
    gemm_kernel<<<ggrid, 256>>>(x_in, W, feat, M, al, ar, D);
    attn_aggr_kernel<<<(N_NODES * NHEADS * 32 + 255) / 256, 256>>>(res, out, D, M, relu);
}

extern "C" void kernel_launch(void* const* d_in, const int* in_sizes, int n_in,
                              void* d_out, int out_size) {
    const float* h     = (const float*)d_in[0];
    const float* W1    = (const float*)d_in[1];
    const float* al1   = (const float*)d_in[2];
    const float* ar1   = (const float*)d_in[3];
    const float* W2    = (const float*)d_in[4];
    const float* al2   = (const float*)d_in[5];
    const float* ar2   = (const float*)d_in[6];
    const float* W3    = (const float*)d_in[7];
    const float* al3   = (const float*)d_in[8];
    const float* ar3   = (const float*)d_in[9];
    const float* resW3 = (const float*)d_in[10];
    const int*   src   = (const int*)d_in[11];
    const int*   dst   = (const int*)d_in[12];
    float* out = (float*)d_out;

    float* g_feat_p; cudaGetSymbolAddress((void**)&g_feat_p, g_feat);
    float* g_x1_p;   cudaGetSymbolAddress((void**)&g_x1_p, g_x1);
    float* g_x2_p;   cudaGetSymbolAddress((void**)&g_x2_p, g_x2);
    float* g_res3_p; cudaGetSymbolAddress((void**)&g_res3_p, g_res3);
    float* g_agg3_p; cudaGetSymbolAddress((void**)&g_agg3_p, g_agg3);

    // CSR build (dst-indexed), reused by all 3 layers
    zero_cnt_kernel<<<(N_NODES + 255) / 256, 256>>>();
    hist_kernel<<<(N_EDGES + 255) / 256, 256>>>(dst);
    scan_kernel<<<1, 1024>>>();
    scatter_kernel<<<(N_EDGES + 255) / 256, 256>>>(src, dst);

    // Layer 1: 128 -> 4x32, residual = input, relu
    run_layer(h, g_feat_p, W1, al1, ar1, h, g_x1_p, 32, 1);
    // Layer 2: 128 -> 4x32, residual = layer-1 output, relu
    run_layer(g_x1_p, g_feat_p, W2, al2, ar2, g_x1_p, g_x2_p, 32, 1);
    // Layer 3 residual projection: x2 @ resW3 (no attention epilogue)
    {
        dim3 ggrid((N_NODES + 63) / 64, 2);
        gemm_kernel<<<ggrid, 256>>>(g_x2_p, resW3, g_res3_p, 256, nullptr, nullptr, 0);
    }
    // Layer 3: 128 -> 4x64, residual = projection, no act
    run_layer(g_x2_p, g_feat_p, W3, al3, ar3, g_res3_p, g_agg3_p, 64, 0);

    // mean over heads -> [N, 64]
    mean_kernel<<<(N_NODES * 64 + 255) / 256, 256>>>(out);
}